// round 13
// baseline (speedup 1.0000x reference)
#include <cuda_runtime.h>
#include <cstdint>

// VectorQuantizer: exact fp32 FFMA2 GEMM, code-broadcast tiling + fused argmin.
// z_e (64,64,64,64) f32, emb (512,64) f32.
// Output (f32): [ z_q : 16777216 ][ vq_loss : 1 ][ indices : 262144 ]

#define KCODES   512
#define DDIM     64
#define HW       4096
#define DHW      262144
#define NPTS     262144
#define LOSS_OFF 16777216
#define IDX_OFF  16777217

#define NCTAS    148
#define NTH      512
#define NW       16
#define TILE_P   64
#define NTILES   (NPTS / TILE_P)        // 4096

// ---- smem layout (bytes) ----
#define OFF_E    0                       // f32 [64 d][512 k] = 131072
#define OFF_ESQ  131072                  // 512 f32
#define OFF_Z    133120                  // 2 bufs x f32 [64 d][64 pt] = 32768
#define OFF_PZ   165888                  // 8 x 64 f32 partial zsq
#define OFF_ZSQ  167936                  // 2 x 64 f32
#define OFF_SLOT 168448                  // 64 pts x 32 slots x u64 = 16384
#define OFF_BI   184832                  // 64 int
#define OFF_RED  185088                  // 16 f32
#define OFF_FLAG 185152
#define OFF_FIN  185160                  // 256 doubles
#define SMEM_SZ  187264

__device__ float g_partials[NCTAS];
__device__ int   g_counter = 0;

__device__ __forceinline__ uint64_t pk2(float lo, float hi) {
    uint64_t r;
    asm("mov.b64 %0, {%1, %2};" : "=l"(r) : "f"(lo), "f"(hi));
    return r;
}
__device__ __forceinline__ float2 upk2(uint64_t v) {
    float2 r;
    asm("mov.b64 {%0, %1}, %2;" : "=f"(r.x), "=f"(r.y) : "l"(v));
    return r;
}
__device__ __forceinline__ void ffma2(uint64_t& d, uint64_t a, uint64_t b) {
    asm("fma.rn.f32x2 %0, %1, %2, %0;" : "+l"(d) : "l"(a), "l"(b));
}

extern "C" __global__ void __launch_bounds__(NTH, 1)
vq_kernel(const float* __restrict__ z, const float* __restrict__ emb,
          float* __restrict__ out)
{
    extern __shared__ char sm[];
    float*    sE    = (float*)(sm + OFF_E);      // [d][k]
    float*    sesq  = (float*)(sm + OFF_ESQ);
    float*    sZ    = (float*)(sm + OFF_Z);      // [buf][d][pt]
    float*    sPZ   = (float*)(sm + OFF_PZ);
    float*    sZSQ  = (float*)(sm + OFF_ZSQ);
    uint64_t* sSLOT = (uint64_t*)(sm + OFF_SLOT); // [pt][32]
    int*      sBI   = (int*)   (sm + OFF_BI);
    float*    sred  = (float*) (sm + OFF_RED);
    int*      sflag = (int*)   (sm + OFF_FLAG);
    double*   sdbl  = (double*)(sm + OFF_FIN);

    const int tid  = threadIdx.x;
    const int wib  = tid >> 5;
    const int lane = tid & 31;
    const int tk   = tid & 63;    // staging/output: point id within tile
    const int tp   = tid >> 6;    // staging/output: dim group

    // ---- codebook -> smem transposed [d][k] ----
    for (int i = tid; i < KCODES * DDIM; i += NTH) {
        int k = i >> 6, d = i & 63;
        sE[d * KCODES + k] = emb[i];
    }
    for (int k = tid; k < KCODES; k += NTH) {
        const float* e = emb + (size_t)k * DDIM;
        float s = 0.f;
        #pragma unroll
        for (int d = 0; d < DDIM; d++) s = fmaf(e[d], e[d], s);
        sesq[k] = s;
    }
    __syncthreads();

    float lsum = 0.f;
    int buf = 0;
    const int t0 = blockIdx.x;

    // ---- stage first tile ----
    if (t0 < NTILES) {
        const int n0  = t0 >> 6;
        const int hw0 = (t0 & 63) * 64;
        float psq = 0.f;
        #pragma unroll
        for (int i2 = 0; i2 < 8; i2++) {
            int d = tp + 8 * i2;
            float v = z[(size_t)n0 * DHW + (size_t)d * HW + hw0 + tk];
            sZ[d * 64 + tk] = v;
            psq = fmaf(v, v, psq);
        }
        sPZ[tp * 64 + tk] = psq;
    }
    __syncthreads();
    if (tid < 64) {
        float s = 0.f;
        #pragma unroll
        for (int g2 = 0; g2 < 8; g2++) s += sPZ[g2 * 64 + tid];
        sZSQ[tid] = s;
    }
    __syncthreads();

    for (int t = t0; t < NTILES; t += NCTAS) {
        const int tn = t + NCTAS;
        const bool pf = (tn < NTILES);

        // ---- prefetch next tile's z into registers ----
        float r[8];
        if (pf) {
            const int n2  = tn >> 6;
            const int hw2 = (tn & 63) * 64;
            #pragma unroll
            for (int i2 = 0; i2 < 8; i2++) {
                int d = tp + 8 * i2;
                r[i2] = z[(size_t)n2 * DHW + (size_t)d * HW + hw2 + tk];
            }
        }

        const float* zc = sZ + buf * 4096;
        const float zsq0 = sZSQ[buf * 64 + 2 * lane];
        const float zsq1 = sZSQ[buf * 64 + 2 * lane + 1];

        // ---- two sweeps of 16 warp-uniform codes each ----
        #pragma unroll
        for (int s = 0; s < 2; s++) {
            const int c0 = s * 256 + wib * 16;

            float esqr[16];
            #pragma unroll
            for (int j = 0; j < 4; j++)
                *(float4*)(esqr + 4 * j) = *(const float4*)(sesq + c0 + 4 * j);

            uint64_t acc[16];
            #pragma unroll
            for (int i2 = 0; i2 < 16; i2++) acc[i2] = 0ull;

            #pragma unroll 8
            for (int d = 0; d < DDIM; d++) {
                float2 zv = *(const float2*)(zc + d * 64 + 2 * lane);
                const ulonglong2* ep =
                    (const ulonglong2*)(sE + d * KCODES + c0);
                ulonglong2 E0 = ep[0];   // code pairs 0,1
                ulonglong2 E1 = ep[1];   // pairs 2,3
                ulonglong2 E2 = ep[2];   // pairs 4,5
                ulonglong2 E3 = ep[3];   // pairs 6,7
                uint64_t z0 = pk2(zv.x, zv.x);
                uint64_t z1 = pk2(zv.y, zv.y);
                ffma2(acc[0],  z0, E0.x); ffma2(acc[1],  z0, E0.y);
                ffma2(acc[2],  z0, E1.x); ffma2(acc[3],  z0, E1.y);
                ffma2(acc[4],  z0, E2.x); ffma2(acc[5],  z0, E2.y);
                ffma2(acc[6],  z0, E3.x); ffma2(acc[7],  z0, E3.y);
                ffma2(acc[8],  z1, E0.x); ffma2(acc[9],  z1, E0.y);
                ffma2(acc[10], z1, E1.x); ffma2(acc[11], z1, E1.y);
                ffma2(acc[12], z1, E2.x); ffma2(acc[13], z1, E2.y);
                ffma2(acc[14], z1, E3.x); ffma2(acc[15], z1, E3.y);
            }

            // ---- per-lane argmin over this sweep's 16 codes, both points ----
            float b0 = 3.4e38f, b1 = 3.4e38f;
            int   i0 = 0, i1 = 0;
            #pragma unroll
            for (int cp = 0; cp < 8; cp++) {
                float2 d0 = upk2(acc[cp]);
                float2 d1 = upk2(acc[cp + 8]);
                float eA = esqr[2 * cp], eB = esqr[2 * cp + 1];
                float v00 = fmaf(-2.0f, d0.x, zsq0 + eA);
                float v01 = fmaf(-2.0f, d0.y, zsq0 + eB);
                float v10 = fmaf(-2.0f, d1.x, zsq1 + eA);
                float v11 = fmaf(-2.0f, d1.y, zsq1 + eB);
                int k0 = c0 + 2 * cp;
                if (v00 < b0) { b0 = v00; i0 = k0; }
                if (v01 < b0) { b0 = v01; i0 = k0 + 1; }
                if (v10 < b1) { b1 = v10; i1 = k0; }
                if (v11 < b1) { b1 = v11; i1 = k0 + 1; }
            }
            // dist > 0 always here (||z-e||^2 with |z|~8) -> float bits monotonic
            sSLOT[(2 * lane)     * 32 + s * 16 + wib] =
                ((uint64_t)__float_as_uint(b0) << 32) | (uint32_t)i0;
            sSLOT[(2 * lane + 1) * 32 + s * 16 + wib] =
                ((uint64_t)__float_as_uint(b1) << 32) | (uint32_t)i1;
        }
        __syncthreads();

        // ---- per-point final argmin over 32 slots ----
        if (tid < 64) {
            const uint64_t* sl = sSLOT + tid * 32;
            uint64_t m = sl[0];
            #pragma unroll
            for (int j = 1; j < 32; j++) m = (sl[j] < m) ? sl[j] : m;
            int k = (int)(uint32_t)m;
            sBI[tid] = k;
            out[IDX_OFF + t * TILE_P + tid] = (float)k;
        }
        __syncthreads();

        // ---- outputs: z_q gather (exact fp32), loss ----
        {
            const int n1  = t >> 6;
            const int hw1 = (t & 63) * 64;
            const int k   = sBI[tk];
            #pragma unroll
            for (int i2 = 0; i2 < 8; i2++) {
                int d = tp + 8 * i2;
                float ev = sE[d * KCODES + k];
                float zv = zc[d * 64 + tk];
                out[(size_t)n1 * DHW + (size_t)d * HW + hw1 + tk] = ev;
                float df = zv - ev;
                lsum = fmaf(df, df, lsum);
            }
        }

        // ---- stage next tile from regs ----
        if (pf) {
            float* zn = sZ + (buf ^ 1) * 4096;
            float psq = 0.f;
            #pragma unroll
            for (int i2 = 0; i2 < 8; i2++) {
                int d = tp + 8 * i2;
                zn[d * 64 + tk] = r[i2];
                psq = fmaf(r[i2], r[i2], psq);
            }
            sPZ[tp * 64 + tk] = psq;
        }
        __syncthreads();
        if (pf && tid < 64) {
            float s = 0.f;
            #pragma unroll
            for (int g2 = 0; g2 < 8; g2++) s += sPZ[g2 * 64 + tid];
            sZSQ[(buf ^ 1) * 64 + tid] = s;
        }
        __syncthreads();
        if (pf) buf ^= 1;
    }

    // ---- loss reduction (deterministic) ----
    #pragma unroll
    for (int off = 16; off > 0; off >>= 1)
        lsum += __shfl_down_sync(0xFFFFFFFFu, lsum, off);
    if (lane == 0) sred[wib] = lsum;
    __syncthreads();
    if (tid == 0) {
        float s = 0.f;
        #pragma unroll
        for (int w = 0; w < NW; w++) s += sred[w];
        g_partials[blockIdx.x] = s;
        __threadfence();
        int prev = atomicAdd(&g_counter, 1);
        *sflag = (prev == NCTAS - 1);
    }
    __syncthreads();

    if (*sflag) {
        if (tid < 256) {
            double v = 0.0;
            if (tid < NCTAS) v = (double)g_partials[tid];
            sdbl[tid] = v;
        }
        __syncthreads();
        #pragma unroll
        for (int off = 128; off > 0; off >>= 1) {
            if (tid < off) sdbl[tid] += sdbl[tid + off];
            __syncthreads();
        }
        if (tid == 0) {
            out[LOSS_OFF] = (float)(sdbl[0] / 16777216.0);
            g_counter = 0;   // graph-replay safe
        }
    }
}

extern "C" void kernel_launch(void* const* d_in, const int* in_sizes, int n_in,
                              void* d_out, int out_size)
{
    const float* z   = (const float*)d_in[0];
    const float* emb = (const float*)d_in[1];
    if (n_in >= 2 && in_sizes[0] < in_sizes[1]) {
        const float* t = z; z = emb; emb = t;
    }
    float* out = (float*)d_out;

    static bool attr_set = false;
    if (!attr_set) {
        cudaFuncSetAttribute(vq_kernel, cudaFuncAttributeMaxDynamicSharedMemorySize,
                             SMEM_SZ);
        attr_set = true;
    }

    vq_kernel<<<NCTAS, NTH, SMEM_SZ>>>(z, emb, out);
}